// round 1
// baseline (speedup 1.0000x reference)
#include <cuda_runtime.h>
#include <mma.h>
#include <cstdint>
#include <cstdio>

using namespace nvcuda;

#define N_TOK 4096
#define DIM   1024
#define NEXP  8
#define HDIM  2048
#define NSLOT (N_TOK * 2)

// ---------------- scratch (device globals; no allocation allowed) ----------
__device__ float g_H[(size_t)NSLOT * HDIM];     // 64 MB: relu(fc1) activations per slot
__device__ int   g_expert_tok[NSLOT];
__device__ float g_expert_w[NSLOT];
__device__ int   g_tok_e[N_TOK * 2];
__device__ float g_tok_w[N_TOK * 2];
__device__ int   g_counts[NEXP];
__device__ int   g_cursor[NEXP];
__device__ int   g_offsets[NEXP + 1];
__device__ float g_colsum[NEXP];
__device__ int   g_top1[NEXP];
__device__ int   g_nt;

// ---------------- init ------------------------------------------------------
__global__ void init_kernel() {
    int t = threadIdx.x;
    if (t < NEXP) {
        g_counts[t] = 0;
        g_cursor[t] = 0;
        g_colsum[t] = 0.f;
        g_top1[t]   = 0;
    }
    if (t == 0) g_nt = 0;
}

// ---------------- gate: fp32 logits, softmax, top2, stats ------------------
__global__ void gate_kernel(const float* __restrict__ x,
                            const unsigned char* __restrict__ pm,
                            const float* __restrict__ gw,
                            float* __restrict__ gate_out) {
    int warp = (blockIdx.x * blockDim.x + threadIdx.x) >> 5;
    int lane = threadIdx.x & 31;
    if (warp >= N_TOK) return;
    const int n = warp;
    const float* xr = x + (size_t)n * DIM;

    float acc[NEXP];
#pragma unroll
    for (int e = 0; e < NEXP; e++) acc[e] = 0.f;

    for (int d = lane; d < DIM; d += 32) {
        float xv = xr[d];
#pragma unroll
        for (int e = 0; e < NEXP; e++) acc[e] += xv * gw[e * DIM + d];
    }
#pragma unroll
    for (int e = 0; e < NEXP; e++) {
#pragma unroll
        for (int o = 16; o > 0; o >>= 1)
            acc[e] += __shfl_xor_sync(0xffffffffu, acc[e], o);
    }

    if (lane == 0) {
        bool masked = (pm[n] != 0);
        float m = acc[0];
#pragma unroll
        for (int e = 1; e < NEXP; e++) m = fmaxf(m, acc[e]);
        float gv[NEXP];
        float s = 0.f;
#pragma unroll
        for (int e = 0; e < NEXP; e++) { gv[e] = expf(acc[e] - m); s += gv[e]; }
        float inv = 1.f / s;
#pragma unroll
        for (int e = 0; e < NEXP; e++) {
            gv[e] *= inv;
            if (masked) gv[e] = 0.f;
            gate_out[(size_t)n * NEXP + e] = gv[e];
        }
        // top-2 (ties -> lowest index, matching jax.lax.top_k)
        int e1 = 0;
#pragma unroll
        for (int e = 1; e < NEXP; e++) if (gv[e] > gv[e1]) e1 = e;
        int e2 = -1;
#pragma unroll
        for (int e = 0; e < NEXP; e++) {
            if (e == e1) continue;
            if (e2 < 0 || gv[e] > gv[e2]) e2 = e;
        }
        float den = gv[e1] + gv[e2];
        if (den == 0.f) den = 1.f;
        float w1 = gv[e1] / den;
        float w2 = gv[e2] / den;

        g_tok_e[2 * n + 0] = e1;
        g_tok_e[2 * n + 1] = e2;
        g_tok_w[2 * n + 0] = w1;
        g_tok_w[2 * n + 1] = w2;

        atomicAdd(&g_counts[e1], 1);
        atomicAdd(&g_counts[e2], 1);
        if (!masked) {
            atomicAdd(&g_top1[e1], 1);
            atomicAdd(&g_nt, 1);
        }
#pragma unroll
        for (int e = 0; e < NEXP; e++) atomicAdd(&g_colsum[e], gv[e]);
    }
}

// ---------------- offsets (exclusive prefix over 8 counts) -----------------
__global__ void offsets_kernel() {
    if (threadIdx.x == 0) {
        int off = 0;
        for (int e = 0; e < NEXP; e++) { g_offsets[e] = off; off += g_counts[e]; }
        g_offsets[NEXP] = off;
    }
}

// ---------------- scatter tokens into per-expert slot lists ----------------
__global__ void scatter_kernel() {
    int n = blockIdx.x * blockDim.x + threadIdx.x;
    if (n >= N_TOK) return;
#pragma unroll
    for (int s = 0; s < 2; s++) {
        int e = g_tok_e[2 * n + s];
        int pos = g_offsets[e] + atomicAdd(&g_cursor[e], 1);
        g_expert_tok[pos] = n;
        g_expert_w[pos]   = g_tok_w[2 * n + s];
    }
}

// ---------------- grouped GEMM1: H = relu(Xg @ W1^T + b1) ------------------
#define BM 64
#define BN 64
#define BK 32
#define ALD 40
#define CLD 68

__global__ void gemm1_kernel(const float* __restrict__ x,
                             const float* __restrict__ w1,
                             const float* __restrict__ b1) {
    const int e = blockIdx.z;
    const int off = g_offsets[e];
    const int cnt = g_offsets[e + 1] - off;
    const int row0 = blockIdx.y * BM;
    if (row0 >= cnt) return;
    const int h0 = blockIdx.x * BN;

    __shared__ float As[BM][ALD];
    __shared__ float Bs[BN][ALD];
    __shared__ float Cs[BM][CLD];

    const int tid = threadIdx.x;         // 128 threads
    const int warp = tid >> 5;
    const int wm = warp & 1;             // 2x2 warp grid, each 32x32
    const int wn = warp >> 1;

    wmma::fragment<wmma::accumulator, 16, 16, 8, float> c[2][2];
#pragma unroll
    for (int i = 0; i < 2; i++)
#pragma unroll
        for (int j = 0; j < 2; j++) wmma::fill_fragment(c[i][j], 0.f);

    const int lrow = tid >> 3;           // 0..15
    const int lcol = (tid & 7) * 4;      // 0..28

    for (int kc = 0; kc < DIM; kc += BK) {
        // load A (gathered token rows), tf32-rounded
#pragma unroll
        for (int r = 0; r < BM; r += 16) {
            int row = r + lrow;
            float4 v = make_float4(0.f, 0.f, 0.f, 0.f);
            if (row0 + row < cnt) {
                int tok = g_expert_tok[off + row0 + row];
                v = *(const float4*)&x[(size_t)tok * DIM + kc + lcol];
            }
            float4 t;
            t.x = wmma::__float_to_tf32(v.x);
            t.y = wmma::__float_to_tf32(v.y);
            t.z = wmma::__float_to_tf32(v.z);
            t.w = wmma::__float_to_tf32(v.w);
            *(float4*)&As[row][lcol] = t;
        }
        // load B rows: fc1_w[(e*H + h), :]
#pragma unroll
        for (int r = 0; r < BN; r += 16) {
            int row = r + lrow;
            float4 v = *(const float4*)&w1[((size_t)(e * HDIM + h0 + row)) * DIM + kc + lcol];
            float4 t;
            t.x = wmma::__float_to_tf32(v.x);
            t.y = wmma::__float_to_tf32(v.y);
            t.z = wmma::__float_to_tf32(v.z);
            t.w = wmma::__float_to_tf32(v.w);
            *(float4*)&Bs[row][lcol] = t;
        }
        __syncthreads();

#pragma unroll
        for (int kk = 0; kk < BK; kk += 8) {
            wmma::fragment<wmma::matrix_a, 16, 16, 8, wmma::precision::tf32, wmma::row_major> a[2];
            wmma::fragment<wmma::matrix_b, 16, 16, 8, wmma::precision::tf32, wmma::col_major> b[2];
            wmma::load_matrix_sync(a[0], &As[wm * 32 + 0][kk], ALD);
            wmma::load_matrix_sync(a[1], &As[wm * 32 + 16][kk], ALD);
            wmma::load_matrix_sync(b[0], &Bs[wn * 32 + 0][kk], ALD);
            wmma::load_matrix_sync(b[1], &Bs[wn * 32 + 16][kk], ALD);
#pragma unroll
            for (int i = 0; i < 2; i++)
#pragma unroll
                for (int j = 0; j < 2; j++)
                    wmma::mma_sync(c[i][j], a[i], b[j], c[i][j]);
        }
        __syncthreads();
    }

    // epilogue: bias + relu -> g_H
#pragma unroll
    for (int i = 0; i < 2; i++)
#pragma unroll
        for (int j = 0; j < 2; j++)
            wmma::store_matrix_sync(&Cs[wm * 32 + i * 16][wn * 32 + j * 16],
                                    c[i][j], CLD, wmma::mem_row_major);
    __syncthreads();

    for (int idx = tid; idx < BM * BN; idx += 128) {
        int r = idx >> 6;
        int cc = idx & 63;
        if (row0 + r < cnt) {
            int h = h0 + cc;
            float v = Cs[r][cc] + b1[e * HDIM + h];
            g_H[(size_t)(off + row0 + r) * HDIM + h] = fmaxf(v, 0.f);
        }
    }
}

// ---------------- grouped GEMM2: out += g * (H @ W2^T + b2) ----------------
__global__ void gemm2_kernel(const float* __restrict__ w2,
                             const float* __restrict__ b2,
                             float* __restrict__ out) {
    const int e = blockIdx.z;
    const int off = g_offsets[e];
    const int cnt = g_offsets[e + 1] - off;
    const int row0 = blockIdx.y * BM;
    if (row0 >= cnt) return;
    const int d0 = blockIdx.x * BN;

    __shared__ float As[BM][ALD];
    __shared__ float Bs[BN][ALD];
    __shared__ float Cs[BM][CLD];

    const int tid = threadIdx.x;
    const int warp = tid >> 5;
    const int wm = warp & 1;
    const int wn = warp >> 1;

    wmma::fragment<wmma::accumulator, 16, 16, 8, float> c[2][2];
#pragma unroll
    for (int i = 0; i < 2; i++)
#pragma unroll
        for (int j = 0; j < 2; j++) wmma::fill_fragment(c[i][j], 0.f);

    const int lrow = tid >> 3;
    const int lcol = (tid & 7) * 4;

    for (int kc = 0; kc < HDIM; kc += BK) {
        // A: contiguous slot rows of g_H
#pragma unroll
        for (int r = 0; r < BM; r += 16) {
            int row = r + lrow;
            float4 v = make_float4(0.f, 0.f, 0.f, 0.f);
            if (row0 + row < cnt) {
                v = *(const float4*)&g_H[(size_t)(off + row0 + row) * HDIM + kc + lcol];
            }
            float4 t;
            t.x = wmma::__float_to_tf32(v.x);
            t.y = wmma::__float_to_tf32(v.y);
            t.z = wmma::__float_to_tf32(v.z);
            t.w = wmma::__float_to_tf32(v.w);
            *(float4*)&As[row][lcol] = t;
        }
        // B rows: fc2_w[(e*D + d), :]
#pragma unroll
        for (int r = 0; r < BN; r += 16) {
            int row = r + lrow;
            float4 v = *(const float4*)&w2[((size_t)(e * DIM + d0 + row)) * HDIM + kc + lcol];
            float4 t;
            t.x = wmma::__float_to_tf32(v.x);
            t.y = wmma::__float_to_tf32(v.y);
            t.z = wmma::__float_to_tf32(v.z);
            t.w = wmma::__float_to_tf32(v.w);
            *(float4*)&Bs[row][lcol] = t;
        }
        __syncthreads();

#pragma unroll
        for (int kk = 0; kk < BK; kk += 8) {
            wmma::fragment<wmma::matrix_a, 16, 16, 8, wmma::precision::tf32, wmma::row_major> a[2];
            wmma::fragment<wmma::matrix_b, 16, 16, 8, wmma::precision::tf32, wmma::col_major> b[2];
            wmma::load_matrix_sync(a[0], &As[wm * 32 + 0][kk], ALD);
            wmma::load_matrix_sync(a[1], &As[wm * 32 + 16][kk], ALD);
            wmma::load_matrix_sync(b[0], &Bs[wn * 32 + 0][kk], ALD);
            wmma::load_matrix_sync(b[1], &Bs[wn * 32 + 16][kk], ALD);
#pragma unroll
            for (int i = 0; i < 2; i++)
#pragma unroll
                for (int j = 0; j < 2; j++)
                    wmma::mma_sync(c[i][j], a[i], b[j], c[i][j]);
        }
        __syncthreads();
    }

#pragma unroll
    for (int i = 0; i < 2; i++)
#pragma unroll
        for (int j = 0; j < 2; j++)
            wmma::store_matrix_sync(&Cs[wm * 32 + i * 16][wn * 32 + j * 16],
                                    c[i][j], CLD, wmma::mem_row_major);
    __syncthreads();

    for (int idx = tid; idx < BM * BN; idx += 128) {
        int r = idx >> 6;
        int cc = idx & 63;
        if (row0 + r < cnt) {
            int slot = off + row0 + r;
            int tok = g_expert_tok[slot];
            float w = g_expert_w[slot];
            int d = d0 + cc;
            float v = (Cs[r][cc] + b2[e * DIM + d]) * w;
            // exactly 2 contributions per (tok,d); fp32 add is commutative -> deterministic
            atomicAdd(&out[(size_t)tok * DIM + d], v);
        }
    }
}

// ---------------- lb_loss ---------------------------------------------------
__global__ void loss_kernel(float* __restrict__ loss_out) {
    if (threadIdx.x == 0) {
        float nt = (float)g_nt;
        float s = 0.f;
        for (int e = 0; e < NEXP; e++)
            s += ((float)g_top1[e] / nt) * (g_colsum[e] / nt);
        *loss_out = (float)NEXP * s;
    }
}

// ---------------- launch -----------------------------------------------------
extern "C" void kernel_launch(void* const* d_in, const int* in_sizes, int n_in,
                              void* d_out, int out_size) {
    const float*         x      = (const float*)d_in[0];
    const unsigned char* pm     = (const unsigned char*)d_in[1];
    const float*         gate_w = (const float*)d_in[2];
    const float*         fc1_w  = (const float*)d_in[3];
    const float*         fc1_b  = (const float*)d_in[4];
    const float*         fc2_w  = (const float*)d_in[5];
    const float*         fc2_b  = (const float*)d_in[6];
    (void)in_sizes; (void)n_in; (void)out_size;

    float* out      = (float*)d_out;
    float* gate_out = out + (size_t)N_TOK * DIM;
    float* loss_out = gate_out + (size_t)N_TOK * NEXP;

    cudaMemsetAsync(out, 0, (size_t)N_TOK * DIM * sizeof(float));
    init_kernel<<<1, 32>>>();
    gate_kernel<<<N_TOK / 8, 256>>>(x, pm, gate_w, gate_out);
    offsets_kernel<<<1, 32>>>();
    scatter_kernel<<<N_TOK / 256, 256>>>();
    gemm1_kernel<<<dim3(HDIM / BN, N_TOK / BM, NEXP), 128>>>(x, fc1_w, fc1_b);
    gemm2_kernel<<<dim3(DIM / BN, N_TOK / BM, NEXP), 128>>>(fc2_w, fc2_b, out);
    loss_kernel<<<1, 32>>>(loss_out);
}